// round 5
// baseline (speedup 1.0000x reference)
#include <cuda_runtime.h>

#define BB 64
#define NP 576
#define DD 512
#define MM 16
#define NCHUNK 18            // 32-patch chunks per batch = 3 blocks x 6 warps

__device__ float    g_scores[BB*BB];
__device__ float    g_pooled[BB*NP];
__device__ float    g_mx [BB*MM*NCHUNK];
__device__ float    g_se [BB*MM*NCHUNK];
__device__ float    g_t5 [BB*MM*NCHUNK*5];
__device__ double   g_accs[2];        // [0]=contrast sum, [1]=mask sum (zero-init, self-resetting)
__device__ unsigned g_bcnt[BB];       // per-batch GEMM-block arrivals (self-resetting)
__device__ unsigned g_mcnt;           // completed batch merges (self-resetting)
__device__ unsigned g_scnt;           // completed score rows (self-resetting)

// ---------------- helpers ----------------
__device__ __forceinline__ float dot4(float4 a, float4 b){
    return a.x*b.x + a.y*b.y + a.z*b.z + a.w*b.w;
}
__device__ __forceinline__ void top5_insert(float t[5], float a){
    #pragma unroll
    for (int q = 0; q < 5; ++q){
        float mx = fmaxf(t[q], a);
        a        = fminf(t[q], a);
        t[q] = mx;
    }
}
__device__ __forceinline__ float warp_top5_sum(float t[5], int lane, float* write5){
    float total = 0.0f;
    #pragma unroll
    for (int it = 0; it < 5; ++it){
        float v = t[0]; int who = lane;
        #pragma unroll
        for (int d = 16; d >= 1; d >>= 1){
            float ov = __shfl_xor_sync(0xffffffffu, v,   d);
            int   ow = __shfl_xor_sync(0xffffffffu, who, d);
            if (ov > v || (ov == v && ow < who)){ v = ov; who = ow; }
        }
        total += v;
        if (write5 && lane == 0) write5[it] = v;
        if (lane == who){ t[0]=t[1]; t[1]=t[2]; t[2]=t[3]; t[3]=t[4]; t[4]=-1e30f; }
    }
    return total;
}
// tf32 MMA: D(16x8,f32) += A(16x8) * B(8x8). fp32 bits passed as tf32 (HW truncates).
__device__ __forceinline__ void mma_tf32(float c[4], float a0, float a1, float a2, float a3,
                                         float b0, float b1){
    asm volatile(
        "mma.sync.aligned.m16n8k8.row.col.f32.tf32.tf32.f32 "
        "{%0,%1,%2,%3}, {%4,%5,%6,%7}, {%8,%9}, {%0,%1,%2,%3};"
        : "+f"(c[0]), "+f"(c[1]), "+f"(c[2]), "+f"(c[3])
        : "r"(__float_as_uint(a0)), "r"(__float_as_uint(a1)),
          "r"(__float_as_uint(a2)), "r"(__float_as_uint(a3)),
          "r"(__float_as_uint(b0)), "r"(__float_as_uint(b1)));
}

// =======================================================================
// Single kernel. grid (4,64), 192 threads.
//  bx<3 : 192-patch x 16-noun tf32 GEMM tile + chunk stats; last arriver
//         of batch b performs the per-batch fine merge.
//  bx==3: score row b; last arriver computes contrastive+triplet, waits
//         for merges, writes out, resets counters.
// =======================================================================
__global__ __launch_bounds__(192, 3)
void k_all(const float* __restrict__ patch, const float* __restrict__ noun,
           const float* __restrict__ img,   const float* __restrict__ txt,
           const float* __restrict__ logit_scale, const int* __restrict__ idx,
           float* __restrict__ out){
    const int b    = blockIdx.y;
    const int lane = threadIdx.x & 31;
    const int w    = threadIdx.x >> 5;       // 0..5
    const int tid  = threadIdx.x;

    __shared__ unsigned s_old;

    if (blockIdx.x == 3){
        // ---------------- score row b ----------------
        const float4* ip = reinterpret_cast<const float4*>(img + (size_t)b * DD);
        float4 a0 = ip[lane], a1 = ip[lane+32], a2 = ip[lane+64], a3 = ip[lane+96];
        for (int j = w; j < BB; j += 6){
            const float4* tp = reinterpret_cast<const float4*>(txt + (size_t)j * DD);
            float s = dot4(a0, tp[lane]) + dot4(a1, tp[lane+32])
                    + dot4(a2, tp[lane+64]) + dot4(a3, tp[lane+96]);
            #pragma unroll
            for (int d = 16; d >= 1; d >>= 1) s += __shfl_xor_sync(0xffffffffu, s, d);
            if (lane == 0) g_scores[b * BB + j] = s;
        }
        __syncthreads();
        if (tid == 0){
            __threadfence();
            s_old = atomicAdd(&g_scnt, 1u);
        }
        __syncthreads();
        if (s_old != 63u) return;

        // ---------------- last score block: contrastive + triplet ----------------
        __shared__ float sc[64][65];
        __shared__ int   sidx[64];
        __shared__ float redc[6];
        __shared__ float redt[6];
        if (tid == 0) __threadfence();
        __syncthreads();

        for (int e = tid; e < 4096; e += 192) sc[e >> 6][e & 63] = g_scores[e];
        if (tid < 64) sidx[tid] = idx[tid];
        __syncthreads();

        const float s = logit_scale[0];

        float contrib = 0.0f;
        for (int r = w; r < 64; r += 6){
            const int myid = sidx[r];
            const int m0 = (sidx[lane]      == myid);
            const int m1 = (sidx[lane + 32] == myid);

            float a0r = s * sc[r][lane], a1r = s * sc[r][lane + 32];
            float mx = fmaxf(a0r, a1r);
            #pragma unroll
            for (int d = 16; d >= 1; d >>= 1) mx = fmaxf(mx, __shfl_xor_sync(0xffffffffu, mx, d));
            float se   = __expf(a0r - mx) + __expf(a1r - mx);
            float ms   = (m0 ? a0r : 0.0f) + (m1 ? a1r : 0.0f);
            float cntf = (float)(m0 + m1);
            #pragma unroll
            for (int d = 16; d >= 1; d >>= 1){
                se   += __shfl_xor_sync(0xffffffffu, se,   d);
                ms   += __shfl_xor_sync(0xffffffffu, ms,   d);
                cntf += __shfl_xor_sync(0xffffffffu, cntf, d);
            }
            float li2t = mx + __logf(se) - ms / cntf;

            float b0r = s * sc[lane][r], b1r = s * sc[lane + 32][r];
            float mxc = fmaxf(b0r, b1r);
            #pragma unroll
            for (int d = 16; d >= 1; d >>= 1) mxc = fmaxf(mxc, __shfl_xor_sync(0xffffffffu, mxc, d));
            float sec = __expf(b0r - mxc) + __expf(b1r - mxc);
            float ms2 = (m0 ? b0r : 0.0f) + (m1 ? b1r : 0.0f);
            #pragma unroll
            for (int d = 16; d >= 1; d >>= 1){
                sec += __shfl_xor_sync(0xffffffffu, sec, d);
                ms2 += __shfl_xor_sync(0xffffffffu, ms2, d);
            }
            float lt2i = mxc + __logf(sec) - ms2 / cntf;

            contrib += 0.5f * (li2t + lt2i);
        }
        if (lane == 0) redc[w] = contrib;

        float mt = 0.0f;
        for (int e = tid; e < 4096; e += 192){
            int i = e >> 6, j = e & 63;
            if (i != j){
                float v = sc[i][j];
                mt += fmaxf(0.0f, 0.1f + v - sc[i][i]) + fmaxf(0.0f, 0.1f + v - sc[j][j]);
            }
        }
        #pragma unroll
        for (int d = 16; d >= 1; d >>= 1) mt += __shfl_xor_sync(0xffffffffu, mt, d);
        if (lane == 0) redt[w] = mt;
        __syncthreads();

        if (tid == 0){
            float c = 0.0f, t = 0.0f;
            #pragma unroll
            for (int i = 0; i < 6; ++i){ c += redc[i]; t += redt[i]; }
            // wait for the 64 per-batch merges
            while (atomicAdd(&g_mcnt, 0u) < 64u) __nanosleep(32);
            __threadfence();
            out[0] = c / 64.0f;
            out[1] = 0.5f * t;
            double contrast = g_accs[0] / (double)(BB * MM);
            double mask     = g_accs[1] / (double)(BB * NP);
            out[2] = (float)(0.6 * contrast + 0.4 * mask);
            // reset for next graph replay (this block is last to touch these)
            g_accs[0] = 0.0; g_accs[1] = 0.0;
            g_mcnt = 0u; g_scnt = 0u;
            __threadfence();
        }
        return;
    }

    // ---------------- GEMM tile: 192 patches x 16 nouns ----------------
    const int q   = lane & 3;       // col-group / k-selector
    const int gid = lane >> 2;      // row-group / noun-selector
    const int rowbase = blockIdx.x * 192 + w * 32;

    const float4* A0 = reinterpret_cast<const float4*>(patch + ((size_t)b*NP + rowbase + gid) * DD);
    const float4* A1 = A0 + 8  * (DD/4);
    const float4* A2 = A0 + 16 * (DD/4);
    const float4* A3 = A0 + 24 * (DD/4);
    const float4* B0 = reinterpret_cast<const float4*>(noun + ((size_t)b*MM + gid) * DD);
    const float4* B1 = B0 + 8 * (DD/4);

    float c00[4] = {0,0,0,0};
    float c01[4] = {0,0,0,0};
    float c10[4] = {0,0,0,0};
    float c11[4] = {0,0,0,0};

    #pragma unroll 4
    for (int p = 0; p < 32; ++p){
        const int o = 4*p + q;
        float4 a0 = A0[o];
        float4 a1 = A1[o];
        float4 a2 = A2[o];
        float4 a3 = A3[o];
        float4 b0 = B0[o];
        float4 b1 = B1[o];
        mma_tf32(c00, a0.x, a1.x, a0.y, a1.y, b0.x, b0.y);
        mma_tf32(c01, a0.x, a1.x, a0.y, a1.y, b1.x, b1.y);
        mma_tf32(c10, a2.x, a3.x, a2.y, a3.y, b0.x, b0.y);
        mma_tf32(c11, a2.x, a3.x, a2.y, a3.y, b1.x, b1.y);
        mma_tf32(c00, a0.z, a1.z, a0.w, a1.w, b0.z, b0.w);
        mma_tf32(c01, a0.z, a1.z, a0.w, a1.w, b1.z, b1.w);
        mma_tf32(c10, a2.z, a3.z, a2.w, a3.w, b0.z, b0.w);
        mma_tf32(c11, a2.z, a3.z, a2.w, a3.w, b1.z, b1.w);
    }

    const float INVT = (float)(1.0 / 0.07);
    #pragma unroll
    for (int i = 0; i < 4; ++i){
        c00[i] *= INVT; c01[i] *= INVT; c10[i] *= INVT; c11[i] *= INVT;
    }

    const int chunk = blockIdx.x * 6 + w;

    // per-noun column stats over this warp's 32 patches
    #pragma unroll
    for (int u = 0; u < 4; ++u){
        float v0, v1, v2, v3; int col;
        if      (u == 0){ col = 2*q;     v0 = c00[0]; v1 = c00[2]; v2 = c10[0]; v3 = c10[2]; }
        else if (u == 1){ col = 2*q + 1; v0 = c00[1]; v1 = c00[3]; v2 = c10[1]; v3 = c10[3]; }
        else if (u == 2){ col = 2*q + 8; v0 = c01[0]; v1 = c01[2]; v2 = c11[0]; v3 = c11[2]; }
        else            { col = 2*q + 9; v0 = c01[1]; v1 = c01[3]; v2 = c11[1]; v3 = c11[3]; }

        float mx = fmaxf(fmaxf(v0, v1), fmaxf(v2, v3));
        #pragma unroll
        for (int d = 4; d <= 16; d <<= 1) mx = fmaxf(mx, __shfl_xor_sync(0xffffffffu, mx, d));
        float se = __expf(v0 - mx) + __expf(v1 - mx) + __expf(v2 - mx) + __expf(v3 - mx);
        #pragma unroll
        for (int d = 4; d <= 16; d <<= 1) se += __shfl_xor_sync(0xffffffffu, se, d);

        float t[5] = {-1e30f, -1e30f, -1e30f, -1e30f, -1e30f};
        top5_insert(t, v0); top5_insert(t, v1); top5_insert(t, v2); top5_insert(t, v3);
        #pragma unroll
        for (int d = 4; d <= 16; d <<= 1){
            float o0 = __shfl_xor_sync(0xffffffffu, t[0], d);
            float o1 = __shfl_xor_sync(0xffffffffu, t[1], d);
            float o2 = __shfl_xor_sync(0xffffffffu, t[2], d);
            float o3 = __shfl_xor_sync(0xffffffffu, t[3], d);
            float o4 = __shfl_xor_sync(0xffffffffu, t[4], d);
            top5_insert(t, o0); top5_insert(t, o1); top5_insert(t, o2);
            top5_insert(t, o3); top5_insert(t, o4);
        }
        if (gid == 0){
            int base = (b * MM + col) * NCHUNK + chunk;
            g_mx[base] = mx;
            g_se[base] = se;
            #pragma unroll
            for (int i = 0; i < 5; ++i) g_t5[base*5 + i] = t[i];
        }
    }

    // pooled row sums over all 16 nouns (scaled space)
    float r0 = c00[0] + c00[1] + c01[0] + c01[1];
    float r1 = c00[2] + c00[3] + c01[2] + c01[3];
    float r2 = c10[0] + c10[1] + c11[0] + c11[1];
    float r3 = c10[2] + c10[3] + c11[2] + c11[3];
    #pragma unroll
    for (int d = 1; d <= 2; d <<= 1){
        r0 += __shfl_xor_sync(0xffffffffu, r0, d);
        r1 += __shfl_xor_sync(0xffffffffu, r1, d);
        r2 += __shfl_xor_sync(0xffffffffu, r2, d);
        r3 += __shfl_xor_sync(0xffffffffu, r3, d);
    }
    if (q == 0){
        float* pp = g_pooled + b * NP + rowbase + gid;
        pp[0]  = r0 * (1.0f/16.0f);
        pp[8]  = r1 * (1.0f/16.0f);
        pp[16] = r2 * (1.0f/16.0f);
        pp[24] = r3 * (1.0f/16.0f);
    }

    // ---------------- arrival; last block of batch b does the fine merge ----------------
    __syncthreads();
    if (tid == 0){
        __threadfence();
        s_old = atomicAdd(&g_bcnt[b], 1u);
    }
    __syncthreads();
    if (s_old != 2u) return;

    if (tid == 0){
        g_bcnt[b] = 0u;            // reset for next replay (no other writer this replay)
        __threadfence();
    }
    __syncthreads();

    __shared__ float s_red[6];
    __shared__ float s_sp[6];
    __shared__ float s_top[6 * 5];

    // part A: per-noun lse + top5 over 18 chunks; nouns m = w, w+6, w+12
    float contrib = 0.0f;
    for (int m = w; m < MM; m += 6){
        const int base = (b * MM + m) * NCHUNK;
        float mxA = (lane < NCHUNK) ? g_mx[base + lane] : -1e30f;
        float mx = mxA;
        #pragma unroll
        for (int d = 16; d >= 1; d >>= 1) mx = fmaxf(mx, __shfl_xor_sync(0xffffffffu, mx, d));
        float se = (lane < NCHUNK) ? g_se[base + lane] * __expf(mxA - mx) : 0.0f;
        #pragma unroll
        for (int d = 16; d >= 1; d >>= 1) se += __shfl_xor_sync(0xffffffffu, se, d);

        float t[5] = {-1e30f, -1e30f, -1e30f, -1e30f, -1e30f};
        if (lane < NCHUNK){
            #pragma unroll
            for (int i = 0; i < 5; ++i) top5_insert(t, g_t5[(base + lane)*5 + i]);
        }
        float tsum = warp_top5_sum(t, lane, nullptr);
        contrib += 5.0f * (mx + __logf(se)) - tsum;
    }
    if (lane == 0) s_red[w] = contrib;

    // part B: pooled softplus + top5 over 576 (3 per thread)
    float u[5] = {-1e30f, -1e30f, -1e30f, -1e30f, -1e30f};
    float sp = 0.0f;
    #pragma unroll
    for (int rep = 0; rep < 3; ++rep){
        int n = tid + rep * 192;
        float x = g_pooled[b * NP + n];
        sp += fmaxf(x, 0.0f) + __logf(1.0f + __expf(-fabsf(x)));
        top5_insert(u, x);
    }
    #pragma unroll
    for (int d = 16; d >= 1; d >>= 1) sp += __shfl_xor_sync(0xffffffffu, sp, d);
    if (lane == 0) s_sp[w] = sp;
    warp_top5_sum(u, lane, &s_top[w * 5]);
    __syncthreads();

    if (w == 0){
        float qq[5] = {-1e30f, -1e30f, -1e30f, -1e30f, -1e30f};
        if (lane < 30) top5_insert(qq, s_top[lane]);
        float ftop = warp_top5_sum(qq, lane, nullptr);

        float spt = (lane < 6) ? s_sp[lane] : 0.0f;
        float crt = (lane < 6) ? s_red[lane] : 0.0f;
        #pragma unroll
        for (int d = 16; d >= 1; d >>= 1){
            spt += __shfl_xor_sync(0xffffffffu, spt, d);
            crt += __shfl_xor_sync(0xffffffffu, crt, d);
        }
        if (lane == 0){
            atomicAdd(&g_accs[0], (double)crt);
            atomicAdd(&g_accs[1], (double)(spt - ftop));
            __threadfence();
            atomicAdd(&g_mcnt, 1u);
        }
    }
}

// =======================================================================
extern "C" void kernel_launch(void* const* d_in, const int* in_sizes, int n_in,
                              void* d_out, int out_size){
    (void)in_sizes; (void)n_in; (void)out_size;
    const float* patch = (const float*)d_in[0];
    const float* noun  = (const float*)d_in[1];
    const float* img   = (const float*)d_in[2];
    const float* txt   = (const float*)d_in[3];
    const float* lsc   = (const float*)d_in[4];
    const int*   idx   = (const int*)d_in[5];
    float* out = (float*)d_out;

    dim3 g(4, 64);
    k_all<<<g, 192>>>(patch, noun, img, txt, lsc, idx, out);
}